// round 14
// baseline (speedup 1.0000x reference)
#include <cuda_runtime.h>
#include <math.h>

#define BB 512
#define SS 50
#define DD 100
#define NSN 12
#define LASTN 3
#define NADJN 12
#define SCALEF 0.1f
#define KR 60    // padded floats per k-row of A/AGG
#define KRU 30   // ulls per k-row

typedef unsigned long long ull;
typedef long long ll;

__device__ __forceinline__ ull pack2(float lo, float hi) {
    ull r; asm("mov.b64 %0, {%1, %2};" : "=l"(r) : "f"(lo), "f"(hi)); return r;
}
__device__ __forceinline__ void unpack2(ull v, float &lo, float &hi) {
    asm("mov.b64 {%0, %1}, %2;" : "=f"(lo), "=f"(hi) : "l"(v));
}
__device__ __forceinline__ void ffma2(ull &d, ull a, ull b) {
    asm("fma.rn.f32x2 %0, %1, %2, %0;" : "+l"(d) : "l"(a), "l"(b));
}
__device__ __forceinline__ void barn(int id) {   // named barrier, 256 threads
    asm volatile("bar.sync %0, 256;" :: "r"(id) : "memory");
}
// column slot for session s in padded k-row: groups of 10 floats, 2-float pad
__device__ __forceinline__ int csl(int s) { return (s / 10) * 12 + (s % 10); }

// smem float offsets (combined block)
#define OA    0        // 6000: h^T padded [d][KR]
#define OADJP 6000     // 5000: adj dup pairs transposed: ull[t*50+s]
#define OC    11000    // 5000: scratch -> hA row-major -> hl row-major [s][100]
#define OAGG  16000    // 6000: agg^T padded [d][KR] -> later G row-major [s][100]
#define OSTAR 22000    // 100
#define OSKV  22100    // 100
#define OVV   22200    // 100
#define OGATE 22300    // 64
#define OMSK  22364    // 64
#define OALPH 22428    // 600
#define ONID  23028    // 600 (int)
#define OSNOD 23628    // 64 (int)
#define ODEN  23692    // 4
#define SMEM_FLOATS 23696
#define SMEM_BYTES  (SMEM_FLOATS * 4)

__global__ void __launch_bounds__(512, 2) k_main(
    const int*   __restrict__ inputs,
    const float* __restrict__ adjm,
    const int*   __restrict__ last_items,
    const int*   __restrict__ adj_items,
    const float* __restrict__ emb,
    const float* __restrict__ sp,
    const float* __restrict__ Wa,
    const float* __restrict__ Wq,
    const float* __restrict__ Wk,
    const float* __restrict__ Wg,
    const float* __restrict__ Wl,
    const int*   __restrict__ adj_all,
    const float* __restrict__ num_w,
    float* __restrict__ out)
{
    extern __shared__ float sm[];
    int tid = threadIdx.x;
    int bid = blockIdx.x;
    const float4* emb4 = (const float4*)emb;

    if (bid < BB) {
        // ============ combined star+global block ============
        int b = bid;
        float* A    = sm + OA;
        float* ADJP = sm + OADJP;
        float* C    = sm + OC;
        float* AGG  = sm + OAGG;   // later reused as G [s][100]
        float* star = sm + OSTAR;
        float* skv  = sm + OSKV;
        float* vv   = sm + OVV;
        float* gate = sm + OGATE;
        float* msk  = sm + OMSK;
        float* alph = sm + OALPH;
        int*   nid  = (int*)(sm + ONID);
        int*   snode= (int*)(sm + OSNOD);
        float* denp = sm + ODEN;

        if (tid < SS) {
            int nd = inputs[b * SS + tid];
            snode[tid] = nd;
            msk[tid] = (nd != 0) ? 1.f : 0.f;
        }
        __syncthreads();

        // ---- L1 (all 512): h gather, adj dup-transpose, nid/alph, denom ----
        if (tid == 0) {
            float c = 0.f;
            #pragma unroll
            for (int s = 0; s < SS; s++) c += msk[s];
            denp[0] = fmaxf(c, 1.f);
        }
        for (int i = tid; i < SS * 25; i += 512) {
            int s = i / 25, q = i - s * 25;
            float4 v = emb4[(ll)snode[s] * 25 + q];
            int cs = csl(s);
            int d = 4 * q;
            A[(d + 0) * KR + cs] = v.x;
            A[(d + 1) * KR + cs] = v.y;
            A[(d + 2) * KR + cs] = v.z;
            A[(d + 3) * KR + cs] = v.w;
        }
        {
            const float* ab = adjm + (ll)b * SS * SS;
            float2* P2v = (float2*)ADJP;
            for (int i = tid; i < SS * SS; i += 512) {
                int s = i / SS, t = i - s * SS;
                float a = ab[i];
                P2v[t * SS + s] = make_float2(a, a);
            }
        }
        for (int i = tid; i < SS * NSN; i += 512) {
            int s = i / NSN, n = i - s * NSN;
            ll nd = snode[s];
            nid[i]  = adj_all[nd * NSN + n];
            alph[i] = num_w[nd * NSN + n];
        }
        __syncthreads();

        // ---- L2: softmax over neighbor weights (50 threads) ----
        if (tid < SS) {
            float* ar = alph + tid * NSN;
            float m = ar[0];
            #pragma unroll
            for (int n = 1; n < NSN; n++) m = fmaxf(m, ar[n]);
            float e[NSN], ssum = 0.f;
            #pragma unroll
            for (int n = 0; n < NSN; n++) { e[n] = expf(ar[n] - m); ssum += e[n]; }
            float inv = 1.f / ssum;
            #pragma unroll
            for (int n = 0; n < NSN; n++) ar[n] = e[n] * inv;
        }
        __syncthreads();

        // ---- L3 (all 512): agg gather ----
        for (int i = tid; i < SS * 25; i += 512) {
            int s = i / 25, q = i - s * 25;
            const float* ar = alph + s * NSN;
            const int*   nr = nid + s * NSN;
            float ax = 0.f, ay = 0.f, az = 0.f, aw = 0.f;
            float4 e[6];
            #pragma unroll
            for (int n = 0; n < 6; n++) e[n] = emb4[(ll)nr[n] * 25 + q];
            #pragma unroll
            for (int n = 0; n < 6; n++) {
                float al = ar[n];
                ax = fmaf(al, e[n].x, ax); ay = fmaf(al, e[n].y, ay);
                az = fmaf(al, e[n].z, az); aw = fmaf(al, e[n].w, aw);
            }
            #pragma unroll
            for (int n = 0; n < 6; n++) e[n] = emb4[(ll)nr[6 + n] * 25 + q];
            #pragma unroll
            for (int n = 0; n < 6; n++) {
                float al = ar[6 + n];
                ax = fmaf(al, e[n].x, ax); ay = fmaf(al, e[n].y, ay);
                az = fmaf(al, e[n].z, az); aw = fmaf(al, e[n].w, aw);
            }
            int cs = csl(s);
            int d = 4 * q;
            AGG[(d + 0) * KR + cs] = ax;
            AGG[(d + 1) * KR + cs] = ay;
            AGG[(d + 2) * KR + cs] = az;
            AGG[(d + 3) * KR + cs] = aw;
        }
        __syncthreads();

        if (tid < 256) {
            // ======================= STAR half (barrier 1) =======================
            int st = tid;
            // P2: star = masked mean
            if (st < DD) {
                float s = 0.f;
                #pragma unroll
                for (int rb = 0; rb < 5; rb++) {
                    #pragma unroll
                    for (int j = 0; j < 10; j++)
                        s = fmaf(A[st * KR + rb * 12 + j], msk[rb * 10 + j], s);
                }
                star[st] = s / denp[0];
            }
            barn(1);
            // P3 partial: skv halves -> C[0..199]
            if (st < 200) {
                int o = st % DD, hh = st / DD, base = hh * 50;
                const float* wc = Wk + o;
                float a0 = 0.f, a1 = 0.f, a2 = 0.f, a3 = 0.f, a4 = 0.f;
                #pragma unroll 1
                for (int j = 0; j < 10; j++) {
                    a0 = fmaf(star[base + j],      wc[(base + j) * DD],      a0);
                    a1 = fmaf(star[base + 10 + j], wc[(base + 10 + j) * DD], a1);
                    a2 = fmaf(star[base + 20 + j], wc[(base + 20 + j) * DD], a2);
                    a3 = fmaf(star[base + 30 + j], wc[(base + 30 + j) * DD], a3);
                    a4 = fmaf(star[base + 40 + j], wc[(base + 40 + j) * DD], a4);
                }
                C[st] = (((a0 + a1) + (a2 + a3)) + a4);
            }
            barn(1);
            if (st < DD) skv[st] = C[st] + C[DD + st];
            barn(1);
            // P4 partial: vv halves -> C[200..399]
            if (st < 200) {
                int o = st % DD, hh = st / DD, base = hh * 50;
                const float* wr = Wq + o * DD + base;
                float a0 = 0.f, a1 = 0.f, a2 = 0.f, a3 = 0.f, a4 = 0.f;
                #pragma unroll 1
                for (int j = 0; j < 10; j++) {
                    a0 = fmaf(wr[j],      skv[base + j],      a0);
                    a1 = fmaf(wr[10 + j], skv[base + 10 + j], a1);
                    a2 = fmaf(wr[20 + j], skv[base + 20 + j], a2);
                    a3 = fmaf(wr[30 + j], skv[base + 30 + j], a3);
                    a4 = fmaf(wr[40 + j], skv[base + 40 + j], a4);
                }
                C[200 + st] = (((a0 + a1) + (a2 + a3)) + a4);
            }
            barn(1);
            if (st < DD) vv[st] = C[200 + st] + C[300 + st];
            barn(1);
            // P5: gate (st<50) + GEMM1 hA = h @ Wa (st<250) -> C
            if (st < SS) {
                int cst = csl(st);
                float a = 0.f;
                #pragma unroll 4
                for (int d = 0; d < DD; d++) a = fmaf(A[d * KR + cst], vv[d], a);
                gate[st] = 1.f / (1.f + expf(-a * SCALEF));
            }
            if (st < 250) {
                int c2 = st % 50, g = st / 50, r0 = g * 10;
                ull acc[5][2];
                #pragma unroll
                for (int rp = 0; rp < 5; rp++) { acc[rp][0] = 0ull; acc[rp][1] = 0ull; }
                const ull* Au = (const ull*)A;
                #pragma unroll 2
                for (int k = 0; k < DD; k++) {
                    float2 w = *(const float2*)&Wa[k * DD + 2 * c2];
                    ull wlo = pack2(w.x, w.x), whi = pack2(w.y, w.y);
                    const ull* xr = Au + k * KRU + g * 6;
                    ulonglong2 xa = *(const ulonglong2*)xr;
                    ulonglong2 xb = *(const ulonglong2*)(xr + 2);
                    ull xc = xr[4];
                    ffma2(acc[0][0], xa.x, wlo); ffma2(acc[0][1], xa.x, whi);
                    ffma2(acc[1][0], xa.y, wlo); ffma2(acc[1][1], xa.y, whi);
                    ffma2(acc[2][0], xb.x, wlo); ffma2(acc[2][1], xb.x, whi);
                    ffma2(acc[3][0], xb.y, wlo); ffma2(acc[3][1], xb.y, whi);
                    ffma2(acc[4][0], xc,   wlo); ffma2(acc[4][1], xc,   whi);
                }
                ull* Cu = (ull*)C;
                #pragma unroll
                for (int rp = 0; rp < 5; rp++) {
                    float v0, v1, u0, u1;
                    unpack2(acc[rp][0], v0, v1);
                    unpack2(acc[rp][1], u0, u1);
                    int r = r0 + 2 * rp;
                    Cu[r * 50 + c2]       = pack2(v0, u0);
                    Cu[(r + 1) * 50 + c2] = pack2(v1, u1);
                }
            }
            barn(1);
            // P6: hn = adj @ hA, hl = (1-g)*hn + g*star
            float hlv[10][2];
            int dp = st % 50, sg = st / 50, s0r = sg * 10;
            if (st < 250) {
                ull hn[10];
                #pragma unroll
                for (int j = 0; j < 10; j++) hn[j] = 0ull;
                const ull* Cu = (const ull*)C;
                const ull* Pu = (const ull*)ADJP;
                #pragma unroll 2
                for (int t = 0; t < SS; t++) {
                    ull xp = Cu[t * 50 + dp];
                    const ulonglong2* pr2 =
                        (const ulonglong2*)(Pu + t * SS + s0r);
                    #pragma unroll
                    for (int j2 = 0; j2 < 5; j2++) {
                        ulonglong2 pp = pr2[j2];
                        ffma2(hn[2 * j2],     xp, pp.x);
                        ffma2(hn[2 * j2 + 1], xp, pp.y);
                    }
                }
                float st0 = star[2 * dp], st1 = star[2 * dp + 1];
                #pragma unroll
                for (int j = 0; j < 10; j++) {
                    float h0, h1;
                    unpack2(hn[j], h0, h1);
                    float gg = gate[s0r + j];
                    hlv[j][0] = (1.f - gg) * h0 + gg * st0;
                    hlv[j][1] = (1.f - gg) * h1 + gg * st1;
                }
            }
            barn(1);   // all reads of C done
            if (st < 250) {
                ull* Cu = (ull*)C;
                #pragma unroll
                for (int j = 0; j < 10; j++)
                    Cu[(s0r + j) * 50 + dp] = pack2(hlv[j][0], hlv[j][1]);
            }
        } else {
            // ============ GLOBAL half: GEMM2 only (barrier 2) ============
            int gt = tid - 256;
            ull acc[5][2];
            int c2 = gt % 50, g = gt / 50, r0 = g * 10;
            if (gt < 250) {
                #pragma unroll
                for (int rp = 0; rp < 5; rp++) { acc[rp][0] = 0ull; acc[rp][1] = 0ull; }
                const ull* Au = (const ull*)A;
                const ull* Bu = (const ull*)AGG;
                #pragma unroll 2
                for (int k = 0; k < DD; k++) {
                    float2 w = *(const float2*)&Wg[k * DD + 2 * c2];
                    ull wlo = pack2(w.x, w.x), whi = pack2(w.y, w.y);
                    const ull* xr = Au + k * KRU + g * 6;
                    ulonglong2 xa = *(const ulonglong2*)xr;
                    ulonglong2 xb = *(const ulonglong2*)(xr + 2);
                    ull xc = xr[4];
                    ffma2(acc[0][0], xa.x, wlo); ffma2(acc[0][1], xa.x, whi);
                    ffma2(acc[1][0], xa.y, wlo); ffma2(acc[1][1], xa.y, whi);
                    ffma2(acc[2][0], xb.x, wlo); ffma2(acc[2][1], xb.x, whi);
                    ffma2(acc[3][0], xb.y, wlo); ffma2(acc[3][1], xb.y, whi);
                    ffma2(acc[4][0], xc,   wlo); ffma2(acc[4][1], xc,   whi);
                }
                #pragma unroll 2
                for (int k = 0; k < DD; k++) {
                    float2 w = *(const float2*)&Wg[(DD + k) * DD + 2 * c2];
                    ull wlo = pack2(w.x, w.x), whi = pack2(w.y, w.y);
                    const ull* xr = Bu + k * KRU + g * 6;
                    ulonglong2 xa = *(const ulonglong2*)xr;
                    ulonglong2 xb = *(const ulonglong2*)(xr + 2);
                    ull xc = xr[4];
                    ffma2(acc[0][0], xa.x, wlo); ffma2(acc[0][1], xa.x, whi);
                    ffma2(acc[1][0], xa.y, wlo); ffma2(acc[1][1], xa.y, whi);
                    ffma2(acc[2][0], xb.x, wlo); ffma2(acc[2][1], xb.x, whi);
                    ffma2(acc[3][0], xb.y, wlo); ffma2(acc[3][1], xb.y, whi);
                    ffma2(acc[4][0], xc,   wlo); ffma2(acc[4][1], xc,   whi);
                }
            }
            barn(2);   // all AGG reads complete -> safe to overwrite with G
            if (gt < 250) {
                ull* Gu = (ull*)AGG;   // reuse as row-major [s][100]
                #pragma unroll
                for (int rp = 0; rp < 5; rp++) {
                    float v0, v1, u0, u1;
                    unpack2(acc[rp][0], v0, v1);
                    unpack2(acc[rp][1], u0, u1);
                    int r = r0 + 2 * rp;
                    Gu[r * 50 + c2]       = pack2(fmaxf(v0, 0.f), fmaxf(u0, 0.f));
                    Gu[(r + 1) * 50 + c2] = pack2(fmaxf(v1, 0.f), fmaxf(u1, 0.f));
                }
            }
        }
        __syncthreads();   // halves rendezvous: C = hl, AGG = G

        // ---- final combine: out = s0*l2n(hl) + s1*l2n(G), float4 path ----
        float* G = AGG;
        float s0 = sp[0], s1 = sp[1];
        int w = tid >> 5, lane = tid & 31;
        const float4* C4 = (const float4*)C;
        const float4* G4 = (const float4*)G;
        float4* out4 = (float4*)out;
        for (int r = w; r < SS; r += 16) {
            float4 x = make_float4(0.f, 0.f, 0.f, 0.f);
            float4 y = make_float4(0.f, 0.f, 0.f, 0.f);
            if (lane < 25) {
                x = C4[r * 25 + lane];
                y = G4[r * 25 + lane];
            }
            float ql = fmaf(x.x, x.x, fmaf(x.y, x.y, fmaf(x.z, x.z, x.w * x.w)));
            float qg = fmaf(y.x, y.x, fmaf(y.y, y.y, fmaf(y.z, y.z, y.w * y.w)));
            #pragma unroll
            for (int o = 16; o > 0; o >>= 1) {
                ql += __shfl_xor_sync(0xffffffffu, ql, o);
                qg += __shfl_xor_sync(0xffffffffu, qg, o);
            }
            float il = s0 / fmaxf(sqrtf(ql), 1e-12f);
            float ig = s1 / fmaxf(sqrtf(qg), 1e-12f);
            if (lane < 25) {
                float4 o4;
                o4.x = x.x * il + y.x * ig;
                o4.y = x.y * il + y.y * ig;
                o4.z = x.z * il + y.z * ig;
                o4.w = x.w * il + y.w * ig;
                out4[((ll)b * SS + r) * 25 + lane] = o4;
            }
        }
    } else {
        // ========================== LAST family ==========================
        int b = bid - BB;
        float* ith = sm;            // 300
        float* ah  = sm + 300;      // 3600
        float* q   = sm + 3900;     // 300
        float* att = sm + 4200;     // 36
        float* out_last = out + (ll)BB * SS * DD;

        for (int i = tid; i < LASTN * 25; i += 512) {
            int l = i / 25, qq = i - l * 25;
            ((float4*)ith)[i] = emb4[(ll)last_items[b * LASTN + l] * 25 + qq];
        }
        for (int i = tid; i < LASTN * NADJN * 25; i += 512) {
            int n = i / 25, qq = i - n * 25;
            ((float4*)ah)[i] = emb4[(ll)adj_items[b * LASTN * NADJN + n] * 25 + qq];
        }
        __syncthreads();

        if (tid < DD) {
            #pragma unroll
            for (int l = 0; l < LASTN; l++) {
                float a = 0.f;
                #pragma unroll 4
                for (int k = 0; k < DD; k++)
                    a = fmaf(ith[l * DD + k], Wl[k * DD + tid], a);
                q[l * DD + tid] = a;
            }
        }
        __syncthreads();

        int w = tid >> 5, lane = tid & 31;
        for (int p = w; p < LASTN * NADJN; p += 16) {
            int l = p / NADJN;
            float s = 0.f;
            for (int d = lane; d < DD; d += 32)
                s = fmaf(q[l * DD + d], ah[p * DD + d], s);
            #pragma unroll
            for (int o = 16; o > 0; o >>= 1)
                s += __shfl_xor_sync(0xffffffffu, s, o);
            if (lane == 0) att[p] = s * SCALEF;
        }
        __syncthreads();

        if (tid < LASTN) {
            float* ar = att + tid * NADJN;
            float m = ar[0];
            #pragma unroll
            for (int n = 1; n < NADJN; n++) m = fmaxf(m, ar[n]);
            float e[NADJN], s = 0.f;
            #pragma unroll
            for (int n = 0; n < NADJN; n++) { e[n] = expf(ar[n] - m); s += e[n]; }
            float inv = 1.f / s;
            #pragma unroll
            for (int n = 0; n < NADJN; n++) ar[n] = e[n] * inv;
        }
        __syncthreads();

        if (tid < DD) {
            float acc = 0.f;
            #pragma unroll
            for (int l = 0; l < LASTN; l++) {
                float a = ith[l * DD + tid];
                #pragma unroll
                for (int n = 0; n < NADJN; n++)
                    a = fmaf(att[l * NADJN + n], ah[(l * NADJN + n) * DD + tid], a);
                acc += a;
            }
            out_last[(ll)b * DD + tid] = acc * (1.f / 3.f);
        }
    }
}

extern "C" void kernel_launch(void* const* d_in, const int* in_sizes, int n_in,
                              void* d_out, int out_size)
{
    const int*   inputs     = (const int*)d_in[0];
    const float* adjm       = (const float*)d_in[1];
    /* d_in[2] = item (unused by the reference) */
    const int*   last_items = (const int*)d_in[3];
    const int*   adj_items  = (const int*)d_in[4];
    const float* emb        = (const float*)d_in[5];
    const float* sp         = (const float*)d_in[6];
    const float* Wa         = (const float*)d_in[7];
    const float* Wq         = (const float*)d_in[8];
    const float* Wk         = (const float*)d_in[9];
    const float* Wg         = (const float*)d_in[10];
    const float* Wl         = (const float*)d_in[11];
    const int*   adj_all    = (const int*)d_in[12];
    const float* num_w      = (const float*)d_in[13];
    float* out = (float*)d_out;

    cudaFuncSetAttribute(k_main, cudaFuncAttributeMaxDynamicSharedMemorySize,
                         SMEM_BYTES);
    k_main<<<2 * BB, 512, SMEM_BYTES>>>(inputs, adjm, last_items, adj_items,
                                        emb, sp, Wa, Wq, Wk, Wg, Wl,
                                        adj_all, num_w, out);
}

// round 15
// speedup vs baseline: 1.2079x; 1.2079x over previous
#include <cuda_runtime.h>
#include <math.h>

#define BB 512
#define SS 50
#define DD 100
#define NSN 12
#define LASTN 3
#define NADJN 12
#define SCALEF 0.1f

typedef unsigned long long ull;
typedef long long ll;

__device__ __forceinline__ ull pack2(float lo, float hi) {
    ull r; asm("mov.b64 %0, {%1, %2};" : "=l"(r) : "f"(lo), "f"(hi)); return r;
}
__device__ __forceinline__ void unpack2(ull v, float &lo, float &hi) {
    asm("mov.b64 {%0, %1}, %2;" : "=f"(lo), "=f"(hi) : "l"(v));
}
__device__ __forceinline__ void ffma2(ull &d, ull a, ull b) {
    asm("fma.rn.f32x2 %0, %1, %2, %0;" : "+l"(d) : "l"(a), "l"(b));
}
__device__ __forceinline__ void barn(int id) {   // named barrier, 256 threads
    asm volatile("bar.sync %0, 256;" :: "r"(id) : "memory");
}

// smem float offsets (combined block)
#define OA    0        // 5000: h^T [d][s]
#define OADJP 5000     // 5000: adj duplicated pairs TRANSPOSED: ull[t*50+s] = (a[s][t], a[s][t])
#define OC    10000    // 5000: scratch -> hA row-major -> hl row-major
#define OAGG  15000    // 5000: agg^T [d][s] -> later G row-major [s][d]
#define OSTAR 20000    // 100
#define OSKV  20100    // 100
#define OVV   20200    // 100
#define OGATE 20300    // 64
#define OMSK  20364    // 64
#define OALPH 20428    // 600
#define ONID  21028    // 600 (int)
#define OSNOD 21628    // 64 (int)
#define ODEN  21692    // 4
#define SMEM_FLOATS 21696
#define SMEM_BYTES  (SMEM_FLOATS * 4)

__global__ void __launch_bounds__(512, 2) k_main(
    const int*   __restrict__ inputs,
    const float* __restrict__ adjm,
    const int*   __restrict__ last_items,
    const int*   __restrict__ adj_items,
    const float* __restrict__ emb,
    const float* __restrict__ sp,
    const float* __restrict__ Wa,
    const float* __restrict__ Wq,
    const float* __restrict__ Wk,
    const float* __restrict__ Wg,
    const float* __restrict__ Wl,
    const int*   __restrict__ adj_all,
    const float* __restrict__ num_w,
    float* __restrict__ out)
{
    extern __shared__ float sm[];
    int tid = threadIdx.x;
    int bid = blockIdx.x;
    const float4* emb4 = (const float4*)emb;

    if (bid < BB) {
        // ============ combined star+global block ============
        int b = bid;
        float* A    = sm + OA;
        float* ADJP = sm + OADJP;
        float* C    = sm + OC;
        float* AGG  = sm + OAGG;   // later reused as G [s][d]
        float* star = sm + OSTAR;
        float* skv  = sm + OSKV;
        float* vv   = sm + OVV;
        float* gate = sm + OGATE;
        float* msk  = sm + OMSK;
        float* alph = sm + OALPH;
        int*   nid  = (int*)(sm + ONID);
        int*   snode= (int*)(sm + OSNOD);
        float* denp = sm + ODEN;

        if (tid < SS) {
            int nd = inputs[b * SS + tid];
            snode[tid] = nd;
            msk[tid] = (nd != 0) ? 1.f : 0.f;
        }
        __syncthreads();

        // ---- L1 (all 512): h gather, adj dup-transpose, nid/alph, denom ----
        if (tid == 0) {
            float c = 0.f;
            #pragma unroll
            for (int s = 0; s < SS; s++) c += msk[s];
            denp[0] = fmaxf(c, 1.f);
        }
        for (int i = tid; i < SS * 25; i += 512) {
            int s = i / 25, q = i - s * 25;
            float4 v = emb4[(ll)snode[s] * 25 + q];
            int d = 4 * q;
            A[(d + 0) * SS + s] = v.x;
            A[(d + 1) * SS + s] = v.y;
            A[(d + 2) * SS + s] = v.z;
            A[(d + 3) * SS + s] = v.w;
        }
        {
            const float* ab = adjm + (ll)b * SS * SS;
            float2* P2v = (float2*)ADJP;
            for (int i = tid; i < SS * SS; i += 512) {
                int s = i / SS, t = i - s * SS;
                float a = ab[i];
                P2v[t * SS + s] = make_float2(a, a);
            }
        }
        for (int i = tid; i < SS * NSN; i += 512) {
            int s = i / NSN, n = i - s * NSN;
            ll nd = snode[s];
            nid[i]  = adj_all[nd * NSN + n];
            alph[i] = num_w[nd * NSN + n];
        }
        __syncthreads();

        // ---- L2: softmax over neighbor weights (50 threads) ----
        if (tid < SS) {
            float* ar = alph + tid * NSN;
            float m = ar[0];
            #pragma unroll
            for (int n = 1; n < NSN; n++) m = fmaxf(m, ar[n]);
            float e[NSN], ssum = 0.f;
            #pragma unroll
            for (int n = 0; n < NSN; n++) { e[n] = expf(ar[n] - m); ssum += e[n]; }
            float inv = 1.f / ssum;
            #pragma unroll
            for (int n = 0; n < NSN; n++) ar[n] = e[n] * inv;
        }
        __syncthreads();

        // ---- L3 (all 512): agg gather, max MLP ----
        for (int i = tid; i < SS * 25; i += 512) {
            int s = i / 25, q = i - s * 25;
            const float* ar = alph + s * NSN;
            const int*   nr = nid + s * NSN;
            float ax = 0.f, ay = 0.f, az = 0.f, aw = 0.f;
            float4 e[6];
            #pragma unroll
            for (int n = 0; n < 6; n++) e[n] = emb4[(ll)nr[n] * 25 + q];
            #pragma unroll
            for (int n = 0; n < 6; n++) {
                float al = ar[n];
                ax = fmaf(al, e[n].x, ax); ay = fmaf(al, e[n].y, ay);
                az = fmaf(al, e[n].z, az); aw = fmaf(al, e[n].w, aw);
            }
            #pragma unroll
            for (int n = 0; n < 6; n++) e[n] = emb4[(ll)nr[6 + n] * 25 + q];
            #pragma unroll
            for (int n = 0; n < 6; n++) {
                float al = ar[6 + n];
                ax = fmaf(al, e[n].x, ax); ay = fmaf(al, e[n].y, ay);
                az = fmaf(al, e[n].z, az); aw = fmaf(al, e[n].w, aw);
            }
            int d = 4 * q;
            AGG[(d + 0) * SS + s] = ax;
            AGG[(d + 1) * SS + s] = ay;
            AGG[(d + 2) * SS + s] = az;
            AGG[(d + 3) * SS + s] = aw;
        }
        __syncthreads();

        if (tid < 256) {
            // ======================= STAR half (barrier 1) =======================
            int st = tid;
            // P2: star = masked mean
            if (st < DD) {
                float s = 0.f;
                #pragma unroll 5
                for (int r = 0; r < SS; r++) s = fmaf(A[st * SS + r], msk[r], s);
                star[st] = s / denp[0];
            }
            barn(1);
            // P3 partial: skv halves -> C[0..199]
            if (st < 200) {
                int o = st % DD, hh = st / DD, base = hh * 50;
                const float* wc = Wk + o;
                float a0 = 0.f, a1 = 0.f, a2 = 0.f, a3 = 0.f, a4 = 0.f;
                #pragma unroll 2
                for (int j = 0; j < 10; j++) {
                    a0 = fmaf(star[base + j],      wc[(base + j) * DD],      a0);
                    a1 = fmaf(star[base + 10 + j], wc[(base + 10 + j) * DD], a1);
                    a2 = fmaf(star[base + 20 + j], wc[(base + 20 + j) * DD], a2);
                    a3 = fmaf(star[base + 30 + j], wc[(base + 30 + j) * DD], a3);
                    a4 = fmaf(star[base + 40 + j], wc[(base + 40 + j) * DD], a4);
                }
                C[st] = (((a0 + a1) + (a2 + a3)) + a4);
            }
            barn(1);
            if (st < DD) skv[st] = C[st] + C[DD + st];
            barn(1);
            // P4 partial: vv halves -> C[200..399]
            if (st < 200) {
                int o = st % DD, hh = st / DD, base = hh * 50;
                const float* wr = Wq + o * DD + base;
                float a0 = 0.f, a1 = 0.f, a2 = 0.f, a3 = 0.f, a4 = 0.f;
                #pragma unroll 2
                for (int j = 0; j < 10; j++) {
                    a0 = fmaf(wr[j],      skv[base + j],      a0);
                    a1 = fmaf(wr[10 + j], skv[base + 10 + j], a1);
                    a2 = fmaf(wr[20 + j], skv[base + 20 + j], a2);
                    a3 = fmaf(wr[30 + j], skv[base + 30 + j], a3);
                    a4 = fmaf(wr[40 + j], skv[base + 40 + j], a4);
                }
                C[200 + st] = (((a0 + a1) + (a2 + a3)) + a4);
            }
            barn(1);
            if (st < DD) vv[st] = C[200 + st] + C[300 + st];
            barn(1);
            // P5: gate (st<50) + GEMM1 hA = h @ Wa (st<250) -> C
            if (st < SS) {
                float a = 0.f;
                #pragma unroll 4
                for (int d = 0; d < DD; d++) a = fmaf(A[d * SS + st], vv[d], a);
                gate[st] = 1.f / (1.f + expf(-a * SCALEF));
            }
            if (st < 250) {
                int c2 = st % 50, g = st / 50, r0 = g * 10;
                ull acc[5][2];
                #pragma unroll
                for (int rp = 0; rp < 5; rp++) { acc[rp][0] = 0ull; acc[rp][1] = 0ull; }
                const ull* Au = (const ull*)A;
                #pragma unroll 5
                for (int k = 0; k < DD; k++) {
                    float2 w = *(const float2*)&Wa[k * DD + 2 * c2];
                    ull wlo = pack2(w.x, w.x), whi = pack2(w.y, w.y);
                    const ull* xr = Au + k * 25 + g * 5;
                    #pragma unroll
                    for (int rp = 0; rp < 5; rp++) {
                        ull xp = xr[rp];
                        ffma2(acc[rp][0], xp, wlo);
                        ffma2(acc[rp][1], xp, whi);
                    }
                }
                #pragma unroll
                for (int rp = 0; rp < 5; rp++) {
                    float v0, v1, u0, u1;
                    unpack2(acc[rp][0], v0, v1);
                    unpack2(acc[rp][1], u0, u1);
                    int r = r0 + 2 * rp;
                    C[r * DD + 2 * c2]           = v0;
                    C[(r + 1) * DD + 2 * c2]     = v1;
                    C[r * DD + 2 * c2 + 1]       = u0;
                    C[(r + 1) * DD + 2 * c2 + 1] = u1;
                }
            }
            barn(1);
            // P6: hn = adj @ hA (ADJP transposed -> LDS.128), hl = (1-g)*hn + g*star
            float hlv[10][2];
            int dp = st % 50, sg = st / 50, s0r = sg * 10;
            if (st < 250) {
                ull hn[10];
                #pragma unroll
                for (int j = 0; j < 10; j++) hn[j] = 0ull;
                const ull* Cu = (const ull*)C;
                const ull* Pu = (const ull*)ADJP;
                #pragma unroll 2
                for (int t = 0; t < SS; t++) {
                    ull xp = Cu[t * (DD / 2) + dp];
                    const ulonglong2* pr2 =
                        (const ulonglong2*)(Pu + t * SS + s0r);
                    #pragma unroll
                    for (int j2 = 0; j2 < 5; j2++) {
                        ulonglong2 pp = pr2[j2];
                        ffma2(hn[2 * j2],     xp, pp.x);
                        ffma2(hn[2 * j2 + 1], xp, pp.y);
                    }
                }
                float st0 = star[2 * dp], st1 = star[2 * dp + 1];
                #pragma unroll
                for (int j = 0; j < 10; j++) {
                    float h0, h1;
                    unpack2(hn[j], h0, h1);
                    float gg = gate[s0r + j];
                    hlv[j][0] = (1.f - gg) * h0 + gg * st0;
                    hlv[j][1] = (1.f - gg) * h1 + gg * st1;
                }
            }
            barn(1);   // all reads of C done
            if (st < 250) {
                #pragma unroll
                for (int j = 0; j < 10; j++) {
                    C[(s0r + j) * DD + 2 * dp]     = hlv[j][0];
                    C[(s0r + j) * DD + 2 * dp + 1] = hlv[j][1];
                }
            }
        } else {
            // ============ GLOBAL half: GEMM2 only (barrier 2) ============
            int gt = tid - 256;
            ull acc[5][2];
            int c2 = gt % 50, g = gt / 50, r0 = g * 10;
            if (gt < 250) {
                #pragma unroll
                for (int rp = 0; rp < 5; rp++) { acc[rp][0] = 0ull; acc[rp][1] = 0ull; }
                const ull* Au = (const ull*)A;
                const ull* Bu = (const ull*)AGG;
                #pragma unroll 5
                for (int k = 0; k < DD; k++) {
                    float2 w = *(const float2*)&Wg[k * DD + 2 * c2];
                    ull wlo = pack2(w.x, w.x), whi = pack2(w.y, w.y);
                    const ull* xr = Au + k * 25 + g * 5;
                    #pragma unroll
                    for (int rp = 0; rp < 5; rp++) {
                        ull xp = xr[rp];
                        ffma2(acc[rp][0], xp, wlo);
                        ffma2(acc[rp][1], xp, whi);
                    }
                }
                #pragma unroll 5
                for (int k = 0; k < DD; k++) {
                    float2 w = *(const float2*)&Wg[(DD + k) * DD + 2 * c2];
                    ull wlo = pack2(w.x, w.x), whi = pack2(w.y, w.y);
                    const ull* xr = Bu + k * 25 + g * 5;
                    #pragma unroll
                    for (int rp = 0; rp < 5; rp++) {
                        ull xp = xr[rp];
                        ffma2(acc[rp][0], xp, wlo);
                        ffma2(acc[rp][1], xp, whi);
                    }
                }
            }
            barn(2);   // all AGG reads complete -> safe to overwrite with G
            if (gt < 250) {
                float* G = AGG;   // reuse
                #pragma unroll
                for (int rp = 0; rp < 5; rp++) {
                    float v0, v1, u0, u1;
                    unpack2(acc[rp][0], v0, v1);
                    unpack2(acc[rp][1], u0, u1);
                    int r = r0 + 2 * rp;
                    G[r * DD + 2 * c2]           = fmaxf(v0, 0.f);
                    G[(r + 1) * DD + 2 * c2]     = fmaxf(v1, 0.f);
                    G[r * DD + 2 * c2 + 1]       = fmaxf(u0, 0.f);
                    G[(r + 1) * DD + 2 * c2 + 1] = fmaxf(u1, 0.f);
                }
            }
        }
        __syncthreads();   // halves rendezvous: C = hl, AGG = G

        // ---- final combine: out = s0*l2n(hl) + s1*l2n(G), float4 path ----
        float* G = AGG;
        float s0 = sp[0], s1 = sp[1];
        int w = tid >> 5, lane = tid & 31;
        const float4* C4 = (const float4*)C;
        const float4* G4 = (const float4*)G;
        float4* out4 = (float4*)out;
        for (int r = w; r < SS; r += 16) {
            float4 x = make_float4(0.f, 0.f, 0.f, 0.f);
            float4 y = make_float4(0.f, 0.f, 0.f, 0.f);
            if (lane < 25) {
                x = C4[r * 25 + lane];
                y = G4[r * 25 + lane];
            }
            float ql = fmaf(x.x, x.x, fmaf(x.y, x.y, fmaf(x.z, x.z, x.w * x.w)));
            float qg = fmaf(y.x, y.x, fmaf(y.y, y.y, fmaf(y.z, y.z, y.w * y.w)));
            #pragma unroll
            for (int o = 16; o > 0; o >>= 1) {
                ql += __shfl_xor_sync(0xffffffffu, ql, o);
                qg += __shfl_xor_sync(0xffffffffu, qg, o);
            }
            float il = s0 / fmaxf(sqrtf(ql), 1e-12f);
            float ig = s1 / fmaxf(sqrtf(qg), 1e-12f);
            if (lane < 25) {
                float4 o4;
                o4.x = x.x * il + y.x * ig;
                o4.y = x.y * il + y.y * ig;
                o4.z = x.z * il + y.z * ig;
                o4.w = x.w * il + y.w * ig;
                out4[((ll)b * SS + r) * 25 + lane] = o4;
            }
        }
    } else {
        // ========================== LAST family ==========================
        int b = bid - BB;
        float* ith = sm;            // 300
        float* ah  = sm + 300;      // 3600
        float* q   = sm + 3900;     // 300
        float* att = sm + 4200;     // 36
        float* out_last = out + (ll)BB * SS * DD;

        for (int i = tid; i < LASTN * 25; i += 512) {
            int l = i / 25, qq = i - l * 25;
            ((float4*)ith)[i] = emb4[(ll)last_items[b * LASTN + l] * 25 + qq];
        }
        for (int i = tid; i < LASTN * NADJN * 25; i += 512) {
            int n = i / 25, qq = i - n * 25;
            ((float4*)ah)[i] = emb4[(ll)adj_items[b * LASTN * NADJN + n] * 25 + qq];
        }
        __syncthreads();

        if (tid < DD) {
            #pragma unroll
            for (int l = 0; l < LASTN; l++) {
                float a = 0.f;
                #pragma unroll 4
                for (int k = 0; k < DD; k++)
                    a = fmaf(ith[l * DD + k], Wl[k * DD + tid], a);
                q[l * DD + tid] = a;
            }
        }
        __syncthreads();

        int w = tid >> 5, lane = tid & 31;
        for (int p = w; p < LASTN * NADJN; p += 16) {
            int l = p / NADJN;
            float s = 0.f;
            for (int d = lane; d < DD; d += 32)
                s = fmaf(q[l * DD + d], ah[p * DD + d], s);
            #pragma unroll
            for (int o = 16; o > 0; o >>= 1)
                s += __shfl_xor_sync(0xffffffffu, s, o);
            if (lane == 0) att[p] = s * SCALEF;
        }
        __syncthreads();

        if (tid < LASTN) {
            float* ar = att + tid * NADJN;
            float m = ar[0];
            #pragma unroll
            for (int n = 1; n < NADJN; n++) m = fmaxf(m, ar[n]);
            float e[NADJN], s = 0.f;
            #pragma unroll
            for (int n = 0; n < NADJN; n++) { e[n] = expf(ar[n] - m); s += e[n]; }
            float inv = 1.f / s;
            #pragma unroll
            for (int n = 0; n < NADJN; n++) ar[n] = e[n] * inv;
        }
        __syncthreads();

        if (tid < DD) {
            float acc = 0.f;
            #pragma unroll
            for (int l = 0; l < LASTN; l++) {
                float a = ith[l * DD + tid];
                #pragma unroll
                for (int n = 0; n < NADJN; n++)
                    a = fmaf(att[l * NADJN + n], ah[(l * NADJN + n) * DD + tid], a);
                acc += a;
            }
            out_last[(ll)b * DD + tid] = acc * (1.f / 3.f);
        }
    }
}

extern "C" void kernel_launch(void* const* d_in, const int* in_sizes, int n_in,
                              void* d_out, int out_size)
{
    const int*   inputs     = (const int*)d_in[0];
    const float* adjm       = (const float*)d_in[1];
    /* d_in[2] = item (unused by the reference) */
    const int*   last_items = (const int*)d_in[3];
    const int*   adj_items  = (const int*)d_in[4];
    const float* emb        = (const float*)d_in[5];
    const float* sp         = (const float*)d_in[6];
    const float* Wa         = (const float*)d_in[7];
    const float* Wq         = (const float*)d_in[8];
    const float* Wk         = (const float*)d_in[9];
    const float* Wg         = (const float*)d_in[10];
    const float* Wl         = (const float*)d_in[11];
    const int*   adj_all    = (const int*)d_in[12];
    const float* num_w      = (const float*)d_in[13];
    float* out = (float*)d_out;

    cudaFuncSetAttribute(k_main, cudaFuncAttributeMaxDynamicSharedMemorySize,
                         SMEM_BYTES);
    k_main<<<2 * BB, 512, SMEM_BYTES>>>(inputs, adjm, last_items, adj_items,
                                        emb, sp, Wa, Wq, Wk, Wg, Wl,
                                        adj_all, num_w, out);
}

// round 16
// speedup vs baseline: 1.2774x; 1.0575x over previous
#include <cuda_runtime.h>
#include <math.h>

#define BB 512
#define SS 50
#define DD 100
#define NSN 12
#define LASTN 3
#define NADJN 12
#define SCALEF 0.1f

typedef unsigned long long ull;
typedef long long ll;

__device__ __forceinline__ ull pack2(float lo, float hi) {
    ull r; asm("mov.b64 %0, {%1, %2};" : "=l"(r) : "f"(lo), "f"(hi)); return r;
}
__device__ __forceinline__ void unpack2(ull v, float &lo, float &hi) {
    asm("mov.b64 {%0, %1}, %2;" : "=f"(lo), "=f"(hi) : "l"(v));
}
__device__ __forceinline__ void ffma2(ull &d, ull a, ull b) {
    asm("fma.rn.f32x2 %0, %1, %2, %0;" : "+l"(d) : "l"(a), "l"(b));
}
__device__ __forceinline__ void barn(int id) {   // named barrier, 256 threads
    asm volatile("bar.sync %0, 256;" :: "r"(id) : "memory");
}

// smem float offsets (combined block)
#define OA    0        // 5000: h^T [d][s]
#define OADJP 5000     // 5000: adj duplicated pairs TRANSPOSED: ull[t*50+s] = (a[s][t], a[s][t])
#define OC    10000    // 5000: scratch -> hA row-major -> hl row-major
#define OAGG  15000    // 5000: agg^T [d][s] -> later G row-major [s][d]
#define OSTAR 20000    // 100
#define OSKV  20100    // 100
#define OVV   20200    // 100
#define OGATE 20300    // 64
#define OMSK  20364    // 64
#define OALPH 20428    // 600
#define ONID  21028    // 600 (int)
#define OSNOD 21628    // 64 (int)
#define ODEN  21692    // 4
#define SMEM_FLOATS 21696
#define SMEM_BYTES  (SMEM_FLOATS * 4)

__global__ void __launch_bounds__(512, 2) k_main(
    const int*   __restrict__ inputs,
    const float* __restrict__ adjm,
    const int*   __restrict__ last_items,
    const int*   __restrict__ adj_items,
    const float* __restrict__ emb,
    const float* __restrict__ sp,
    const float* __restrict__ Wa,
    const float* __restrict__ Wq,
    const float* __restrict__ Wk,
    const float* __restrict__ Wg,
    const float* __restrict__ Wl,
    const int*   __restrict__ adj_all,
    const float* __restrict__ num_w,
    float* __restrict__ out)
{
    extern __shared__ float sm[];
    int tid = threadIdx.x;
    int bid = blockIdx.x;
    const float4* emb4 = (const float4*)emb;

    if (bid < BB) {
        // ============ combined star+global block ============
        int b = bid;
        float* A    = sm + OA;
        float* ADJP = sm + OADJP;
        float* C    = sm + OC;
        float* AGG  = sm + OAGG;   // later reused as G [s][d]
        float* star = sm + OSTAR;
        float* skv  = sm + OSKV;
        float* vv   = sm + OVV;
        float* gate = sm + OGATE;
        float* msk  = sm + OMSK;
        float* alph = sm + OALPH;
        int*   nid  = (int*)(sm + ONID);
        int*   snode= (int*)(sm + OSNOD);
        float* denp = sm + ODEN;

        if (tid < SS) {
            int nd = inputs[b * SS + tid];
            snode[tid] = nd;
            msk[tid] = (nd != 0) ? 1.f : 0.f;
        }
        __syncthreads();

        // ---- L1 (all 512): h gather, adj dup-transpose, nid/alph, denom ----
        if (tid == 0) {
            float c = 0.f;
            #pragma unroll
            for (int s = 0; s < SS; s++) c += msk[s];
            denp[0] = fmaxf(c, 1.f);
        }
        for (int i = tid; i < SS * 25; i += 512) {
            int s = i / 25, q = i - s * 25;
            float4 v = emb4[(ll)snode[s] * 25 + q];
            int d = 4 * q;
            A[(d + 0) * SS + s] = v.x;
            A[(d + 1) * SS + s] = v.y;
            A[(d + 2) * SS + s] = v.z;
            A[(d + 3) * SS + s] = v.w;
        }
        {
            const float* ab = adjm + (ll)b * SS * SS;
            float2* P2v = (float2*)ADJP;
            for (int i = tid; i < SS * SS; i += 512) {
                int s = i / SS, t = i - s * SS;
                float a = ab[i];
                P2v[t * SS + s] = make_float2(a, a);
            }
        }
        for (int i = tid; i < SS * NSN; i += 512) {
            int s = i / NSN, n = i - s * NSN;
            ll nd = snode[s];
            nid[i]  = adj_all[nd * NSN + n];
            alph[i] = num_w[nd * NSN + n];
        }
        __syncthreads();

        // ---- L2: softmax over neighbor weights (50 threads) ----
        if (tid < SS) {
            float* ar = alph + tid * NSN;
            float m = ar[0];
            #pragma unroll
            for (int n = 1; n < NSN; n++) m = fmaxf(m, ar[n]);
            float e[NSN], ssum = 0.f;
            #pragma unroll
            for (int n = 0; n < NSN; n++) { e[n] = expf(ar[n] - m); ssum += e[n]; }
            float inv = 1.f / ssum;
            #pragma unroll
            for (int n = 0; n < NSN; n++) ar[n] = e[n] * inv;
        }
        __syncthreads();

        // ---- L3 (all 512): agg gather, max MLP ----
        for (int i = tid; i < SS * 25; i += 512) {
            int s = i / 25, q = i - s * 25;
            const float* ar = alph + s * NSN;
            const int*   nr = nid + s * NSN;
            float ax = 0.f, ay = 0.f, az = 0.f, aw = 0.f;
            float4 e[6];
            #pragma unroll
            for (int n = 0; n < 6; n++) e[n] = emb4[(ll)nr[n] * 25 + q];
            #pragma unroll
            for (int n = 0; n < 6; n++) {
                float al = ar[n];
                ax = fmaf(al, e[n].x, ax); ay = fmaf(al, e[n].y, ay);
                az = fmaf(al, e[n].z, az); aw = fmaf(al, e[n].w, aw);
            }
            #pragma unroll
            for (int n = 0; n < 6; n++) e[n] = emb4[(ll)nr[6 + n] * 25 + q];
            #pragma unroll
            for (int n = 0; n < 6; n++) {
                float al = ar[6 + n];
                ax = fmaf(al, e[n].x, ax); ay = fmaf(al, e[n].y, ay);
                az = fmaf(al, e[n].z, az); aw = fmaf(al, e[n].w, aw);
            }
            int d = 4 * q;
            AGG[(d + 0) * SS + s] = ax;
            AGG[(d + 1) * SS + s] = ay;
            AGG[(d + 2) * SS + s] = az;
            AGG[(d + 3) * SS + s] = aw;
        }
        __syncthreads();

        if (tid < 256) {
            // ======================= STAR half (barrier 1) =======================
            int st = tid;
            // P2: star = masked mean
            if (st < DD) {
                float s = 0.f;
                #pragma unroll 5
                for (int r = 0; r < SS; r++) s = fmaf(A[st * SS + r], msk[r], s);
                star[st] = s / denp[0];
            }
            barn(1);
            // P3 partial: skv halves -> C[0..199]
            if (st < 200) {
                int o = st % DD, hh = st / DD, base = hh * 50;
                const float* wc = Wk + o;
                float a0 = 0.f, a1 = 0.f, a2 = 0.f, a3 = 0.f, a4 = 0.f;
                #pragma unroll 5
                for (int j = 0; j < 10; j++) {
                    a0 = fmaf(star[base + j],      wc[(base + j) * DD],      a0);
                    a1 = fmaf(star[base + 10 + j], wc[(base + 10 + j) * DD], a1);
                    a2 = fmaf(star[base + 20 + j], wc[(base + 20 + j) * DD], a2);
                    a3 = fmaf(star[base + 30 + j], wc[(base + 30 + j) * DD], a3);
                    a4 = fmaf(star[base + 40 + j], wc[(base + 40 + j) * DD], a4);
                }
                C[st] = (((a0 + a1) + (a2 + a3)) + a4);
            }
            barn(1);
            if (st < DD) skv[st] = C[st] + C[DD + st];
            barn(1);
            // P4 partial: vv halves -> C[200..399]
            if (st < 200) {
                int o = st % DD, hh = st / DD, base = hh * 50;
                const float* wr = Wq + o * DD + base;
                float a0 = 0.f, a1 = 0.f, a2 = 0.f, a3 = 0.f, a4 = 0.f;
                #pragma unroll 5
                for (int j = 0; j < 10; j++) {
                    a0 = fmaf(wr[j],      skv[base + j],      a0);
                    a1 = fmaf(wr[10 + j], skv[base + 10 + j], a1);
                    a2 = fmaf(wr[20 + j], skv[base + 20 + j], a2);
                    a3 = fmaf(wr[30 + j], skv[base + 30 + j], a3);
                    a4 = fmaf(wr[40 + j], skv[base + 40 + j], a4);
                }
                C[200 + st] = (((a0 + a1) + (a2 + a3)) + a4);
            }
            barn(1);
            if (st < DD) vv[st] = C[200 + st] + C[300 + st];
            barn(1);
            // P5: gate (st<50) + GEMM1 hA = h @ Wa (st<250) -> C
            if (st < SS) {
                float a = 0.f;
                #pragma unroll 4
                for (int d = 0; d < DD; d++) a = fmaf(A[d * SS + st], vv[d], a);
                gate[st] = 1.f / (1.f + expf(-a * SCALEF));
            }
            if (st < 250) {
                int c2 = st % 50, g = st / 50, r0 = g * 10;
                ull acc[5][2];
                #pragma unroll
                for (int rp = 0; rp < 5; rp++) { acc[rp][0] = 0ull; acc[rp][1] = 0ull; }
                const ull* Au = (const ull*)A;
                #pragma unroll 5
                for (int k = 0; k < DD; k++) {
                    float2 w = *(const float2*)&Wa[k * DD + 2 * c2];
                    ull wlo = pack2(w.x, w.x), whi = pack2(w.y, w.y);
                    const ull* xr = Au + k * 25 + g * 5;
                    #pragma unroll
                    for (int rp = 0; rp < 5; rp++) {
                        ull xp = xr[rp];
                        ffma2(acc[rp][0], xp, wlo);
                        ffma2(acc[rp][1], xp, whi);
                    }
                }
                #pragma unroll
                for (int rp = 0; rp < 5; rp++) {
                    float v0, v1, u0, u1;
                    unpack2(acc[rp][0], v0, v1);
                    unpack2(acc[rp][1], u0, u1);
                    int r = r0 + 2 * rp;
                    C[r * DD + 2 * c2]           = v0;
                    C[(r + 1) * DD + 2 * c2]     = v1;
                    C[r * DD + 2 * c2 + 1]       = u0;
                    C[(r + 1) * DD + 2 * c2 + 1] = u1;
                }
            }
            barn(1);
            // P6: hn = adj @ hA (ADJP transposed -> LDS.128), hl = (1-g)*hn + g*star
            float hlv[10][2];
            int dp = st % 50, sg = st / 50, s0r = sg * 10;
            if (st < 250) {
                ull hn[10];
                #pragma unroll
                for (int j = 0; j < 10; j++) hn[j] = 0ull;
                const ull* Cu = (const ull*)C;
                const ull* Pu = (const ull*)ADJP;
                #pragma unroll 2
                for (int t = 0; t < SS; t++) {
                    ull xp = Cu[t * (DD / 2) + dp];
                    const ulonglong2* pr2 =
                        (const ulonglong2*)(Pu + t * SS + s0r);
                    #pragma unroll
                    for (int j2 = 0; j2 < 5; j2++) {
                        ulonglong2 pp = pr2[j2];
                        ffma2(hn[2 * j2],     xp, pp.x);
                        ffma2(hn[2 * j2 + 1], xp, pp.y);
                    }
                }
                float st0 = star[2 * dp], st1 = star[2 * dp + 1];
                #pragma unroll
                for (int j = 0; j < 10; j++) {
                    float h0, h1;
                    unpack2(hn[j], h0, h1);
                    float gg = gate[s0r + j];
                    hlv[j][0] = (1.f - gg) * h0 + gg * st0;
                    hlv[j][1] = (1.f - gg) * h1 + gg * st1;
                }
            }
            barn(1);   // all reads of C done
            if (st < 250) {
                #pragma unroll
                for (int j = 0; j < 10; j++) {
                    C[(s0r + j) * DD + 2 * dp]     = hlv[j][0];
                    C[(s0r + j) * DD + 2 * dp + 1] = hlv[j][1];
                }
            }
        } else {
            // ============ GLOBAL half: GEMM2 only (barrier 2) ============
            int gt = tid - 256;
            ull acc[5][2];
            int c2 = gt % 50, g = gt / 50, r0 = g * 10;
            if (gt < 250) {
                #pragma unroll
                for (int rp = 0; rp < 5; rp++) { acc[rp][0] = 0ull; acc[rp][1] = 0ull; }
                const ull* Au = (const ull*)A;
                const ull* Bu = (const ull*)AGG;
                #pragma unroll 5
                for (int k = 0; k < DD; k++) {
                    float2 w = *(const float2*)&Wg[k * DD + 2 * c2];
                    ull wlo = pack2(w.x, w.x), whi = pack2(w.y, w.y);
                    const ull* xr = Au + k * 25 + g * 5;
                    #pragma unroll
                    for (int rp = 0; rp < 5; rp++) {
                        ull xp = xr[rp];
                        ffma2(acc[rp][0], xp, wlo);
                        ffma2(acc[rp][1], xp, whi);
                    }
                }
                #pragma unroll 5
                for (int k = 0; k < DD; k++) {
                    float2 w = *(const float2*)&Wg[(DD + k) * DD + 2 * c2];
                    ull wlo = pack2(w.x, w.x), whi = pack2(w.y, w.y);
                    const ull* xr = Bu + k * 25 + g * 5;
                    #pragma unroll
                    for (int rp = 0; rp < 5; rp++) {
                        ull xp = xr[rp];
                        ffma2(acc[rp][0], xp, wlo);
                        ffma2(acc[rp][1], xp, whi);
                    }
                }
            }
            barn(2);   // all AGG reads complete -> safe to overwrite with G
            if (gt < 250) {
                float* G = AGG;   // reuse
                #pragma unroll
                for (int rp = 0; rp < 5; rp++) {
                    float v0, v1, u0, u1;
                    unpack2(acc[rp][0], v0, v1);
                    unpack2(acc[rp][1], u0, u1);
                    int r = r0 + 2 * rp;
                    G[r * DD + 2 * c2]           = fmaxf(v0, 0.f);
                    G[(r + 1) * DD + 2 * c2]     = fmaxf(v1, 0.f);
                    G[r * DD + 2 * c2 + 1]       = fmaxf(u0, 0.f);
                    G[(r + 1) * DD + 2 * c2 + 1] = fmaxf(u1, 0.f);
                }
            }
        }
        __syncthreads();   // halves rendezvous: C = hl, AGG = G

        // ---- final combine: out = s0*l2n(hl) + s1*l2n(G), float4 path ----
        float* G = AGG;
        float s0 = sp[0], s1 = sp[1];
        int w = tid >> 5, lane = tid & 31;
        const float4* C4 = (const float4*)C;
        const float4* G4 = (const float4*)G;
        float4* out4 = (float4*)out;
        for (int r = w; r < SS; r += 16) {
            float4 x = make_float4(0.f, 0.f, 0.f, 0.f);
            float4 y = make_float4(0.f, 0.f, 0.f, 0.f);
            if (lane < 25) {
                x = C4[r * 25 + lane];
                y = G4[r * 25 + lane];
            }
            float ql = fmaf(x.x, x.x, fmaf(x.y, x.y, fmaf(x.z, x.z, x.w * x.w)));
            float qg = fmaf(y.x, y.x, fmaf(y.y, y.y, fmaf(y.z, y.z, y.w * y.w)));
            #pragma unroll
            for (int o = 16; o > 0; o >>= 1) {
                ql += __shfl_xor_sync(0xffffffffu, ql, o);
                qg += __shfl_xor_sync(0xffffffffu, qg, o);
            }
            float il = s0 / fmaxf(sqrtf(ql), 1e-12f);
            float ig = s1 / fmaxf(sqrtf(qg), 1e-12f);
            if (lane < 25) {
                float4 o4;
                o4.x = x.x * il + y.x * ig;
                o4.y = x.y * il + y.y * ig;
                o4.z = x.z * il + y.z * ig;
                o4.w = x.w * il + y.w * ig;
                out4[((ll)b * SS + r) * 25 + lane] = o4;
            }
        }
    } else {
        // ========================== LAST family ==========================
        int b = bid - BB;
        float* ith = sm;            // 300
        float* ah  = sm + 300;      // 3600
        float* q   = sm + 3900;     // 300
        float* att = sm + 4200;     // 36
        float* out_last = out + (ll)BB * SS * DD;

        for (int i = tid; i < LASTN * 25; i += 512) {
            int l = i / 25, qq = i - l * 25;
            ((float4*)ith)[i] = emb4[(ll)last_items[b * LASTN + l] * 25 + qq];
        }
        for (int i = tid; i < LASTN * NADJN * 25; i += 512) {
            int n = i / 25, qq = i - n * 25;
            ((float4*)ah)[i] = emb4[(ll)adj_items[b * LASTN * NADJN + n] * 25 + qq];
        }
        __syncthreads();

        if (tid < DD) {
            #pragma unroll
            for (int l = 0; l < LASTN; l++) {
                float a0 = 0.f, a1 = 0.f, a2 = 0.f, a3 = 0.f;
                #pragma unroll 5
                for (int k = 0; k < DD; k += 4) {
                    a0 = fmaf(ith[l * DD + k],     Wl[k * DD + tid],       a0);
                    a1 = fmaf(ith[l * DD + k + 1], Wl[(k + 1) * DD + tid], a1);
                    a2 = fmaf(ith[l * DD + k + 2], Wl[(k + 2) * DD + tid], a2);
                    a3 = fmaf(ith[l * DD + k + 3], Wl[(k + 3) * DD + tid], a3);
                }
                q[l * DD + tid] = (a0 + a1) + (a2 + a3);
            }
        }
        __syncthreads();

        int w = tid >> 5, lane = tid & 31;
        for (int p = w; p < LASTN * NADJN; p += 16) {
            int l = p / NADJN;
            float s = 0.f;
            for (int d = lane; d < DD; d += 32)
                s = fmaf(q[l * DD + d], ah[p * DD + d], s);
            #pragma unroll
            for (int o = 16; o > 0; o >>= 1)
                s += __shfl_xor_sync(0xffffffffu, s, o);
            if (lane == 0) att[p] = s * SCALEF;
        }
        __syncthreads();

        if (tid < LASTN) {
            float* ar = att + tid * NADJN;
            float m = ar[0];
            #pragma unroll
            for (int n = 1; n < NADJN; n++) m = fmaxf(m, ar[n]);
            float e[NADJN], s = 0.f;
            #pragma unroll
            for (int n = 0; n < NADJN; n++) { e[n] = expf(ar[n] - m); s += e[n]; }
            float inv = 1.f / s;
            #pragma unroll
            for (int n = 0; n < NADJN; n++) ar[n] = e[n] * inv;
        }
        __syncthreads();

        if (tid < DD) {
            float acc = 0.f;
            #pragma unroll
            for (int l = 0; l < LASTN; l++) {
                float a = ith[l * DD + tid];
                #pragma unroll
                for (int n = 0; n < NADJN; n++)
                    a = fmaf(att[l * NADJN + n], ah[(l * NADJN + n) * DD + tid], a);
                acc += a;
            }
            out_last[(ll)b * DD + tid] = acc * (1.f / 3.f);
        }
    }
}

extern "C" void kernel_launch(void* const* d_in, const int* in_sizes, int n_in,
                              void* d_out, int out_size)
{
    const int*   inputs     = (const int*)d_in[0];
    const float* adjm       = (const float*)d_in[1];
    /* d_in[2] = item (unused by the reference) */
    const int*   last_items = (const int*)d_in[3];
    const int*   adj_items  = (const int*)d_in[4];
    const float* emb        = (const float*)d_in[5];
    const float* sp         = (const float*)d_in[6];
    const float* Wa         = (const float*)d_in[7];
    const float* Wq         = (const float*)d_in[8];
    const float* Wk         = (const float*)d_in[9];
    const float* Wg         = (const float*)d_in[10];
    const float* Wl         = (const float*)d_in[11];
    const int*   adj_all    = (const int*)d_in[12];
    const float* num_w      = (const float*)d_in[13];
    float* out = (float*)d_out;

    cudaFuncSetAttribute(k_main, cudaFuncAttributeMaxDynamicSharedMemorySize,
                         SMEM_BYTES);
    k_main<<<2 * BB, 512, SMEM_BYTES>>>(inputs, adjm, last_items, adj_items,
                                        emb, sp, Wa, Wq, Wk, Wg, Wl,
                                        adj_all, num_w, out);
}

// round 17
// speedup vs baseline: 1.2952x; 1.0140x over previous
#include <cuda_runtime.h>
#include <math.h>

#define BB 512
#define SS 50
#define DD 100
#define NSN 12
#define LASTN 3
#define NADJN 12
#define SCALEF 0.1f

typedef unsigned long long ull;
typedef long long ll;

__device__ __forceinline__ ull pack2(float lo, float hi) {
    ull r; asm("mov.b64 %0, {%1, %2};" : "=l"(r) : "f"(lo), "f"(hi)); return r;
}
__device__ __forceinline__ void unpack2(ull v, float &lo, float &hi) {
    asm("mov.b64 {%0, %1}, %2;" : "=f"(lo), "=f"(hi) : "l"(v));
}
__device__ __forceinline__ void ffma2(ull &d, ull a, ull b) {
    asm("fma.rn.f32x2 %0, %1, %2, %0;" : "+l"(d) : "l"(a), "l"(b));
}
__device__ __forceinline__ void barn(int id) {   // named barrier, 256 threads
    asm volatile("bar.sync %0, 256;" :: "r"(id) : "memory");
}

// smem float offsets (combined block)
#define OA    0        // 5000: h^T [d][s]
#define OADJP 5000     // 5000: adj duplicated pairs TRANSPOSED: ull[t*50+s] = (a[s][t], a[s][t])
#define OC    10000    // 5000: scratch -> hA row-major -> hl row-major
#define OAGG  15000    // 5000: agg^T [d][s] -> later G row-major [s][d]
#define OSTAR 20000    // 100
#define OSKV  20100    // 100
#define OVV   20200    // 100
#define OGATE 20300    // 64
#define OMSK  20364    // 64
#define OALPH 20428    // 600
#define ONID  21028    // 600 (int)
#define OSNOD 21628    // 64 (int)
#define ODEN  21692    // 4
#define SMEM_FLOATS 21696
#define SMEM_BYTES  (SMEM_FLOATS * 4)

__global__ void __launch_bounds__(512, 2) k_main(
    const int*   __restrict__ inputs,
    const float* __restrict__ adjm,
    const int*   __restrict__ last_items,
    const int*   __restrict__ adj_items,
    const float* __restrict__ emb,
    const float* __restrict__ sp,
    const float* __restrict__ Wa,
    const float* __restrict__ Wq,
    const float* __restrict__ Wk,
    const float* __restrict__ Wg,
    const float* __restrict__ Wl,
    const int*   __restrict__ adj_all,
    const float* __restrict__ num_w,
    float* __restrict__ out)
{
    extern __shared__ float sm[];
    int tid = threadIdx.x;
    int bid = blockIdx.x;
    const float4* emb4 = (const float4*)emb;

    if (bid < BB) {
        // ============ combined star+global block ============
        int b = bid;
        float* A    = sm + OA;
        float* ADJP = sm + OADJP;
        float* C    = sm + OC;
        float* AGG  = sm + OAGG;   // later reused as G [s][d]
        float* star = sm + OSTAR;
        float* skv  = sm + OSKV;
        float* vv   = sm + OVV;
        float* gate = sm + OGATE;
        float* msk  = sm + OMSK;
        float* alph = sm + OALPH;
        int*   nid  = (int*)(sm + ONID);
        int*   snode= (int*)(sm + OSNOD);
        float* denp = sm + ODEN;

        if (tid < SS) {
            int nd = inputs[b * SS + tid];
            snode[tid] = nd;
            msk[tid] = (nd != 0) ? 1.f : 0.f;
        }
        __syncthreads();

        // ---- L1 (all 512): h gather, adj dup-transpose, nid/alph, denom ----
        if (tid == 0) {
            float c = 0.f;
            #pragma unroll
            for (int s = 0; s < SS; s++) c += msk[s];
            denp[0] = fmaxf(c, 1.f);
        }
        for (int i = tid; i < SS * 25; i += 512) {
            int s = i / 25, q = i - s * 25;
            float4 v = emb4[(ll)snode[s] * 25 + q];
            int d = 4 * q;
            A[(d + 0) * SS + s] = v.x;
            A[(d + 1) * SS + s] = v.y;
            A[(d + 2) * SS + s] = v.z;
            A[(d + 3) * SS + s] = v.w;
        }
        {
            const float* ab = adjm + (ll)b * SS * SS;
            float2* P2v = (float2*)ADJP;
            for (int i = tid; i < SS * SS; i += 512) {
                int s = i / SS, t = i - s * SS;
                float a = ab[i];
                P2v[t * SS + s] = make_float2(a, a);
            }
        }
        for (int i = tid; i < SS * NSN; i += 512) {
            int s = i / NSN, n = i - s * NSN;
            ll nd = snode[s];
            nid[i]  = adj_all[nd * NSN + n];
            alph[i] = num_w[nd * NSN + n];
        }
        __syncthreads();

        // ---- L2: softmax over neighbor weights (50 threads) ----
        if (tid < SS) {
            float* ar = alph + tid * NSN;
            float m = ar[0];
            #pragma unroll
            for (int n = 1; n < NSN; n++) m = fmaxf(m, ar[n]);
            float e[NSN], ssum = 0.f;
            #pragma unroll
            for (int n = 0; n < NSN; n++) { e[n] = expf(ar[n] - m); ssum += e[n]; }
            float inv = 1.f / ssum;
            #pragma unroll
            for (int n = 0; n < NSN; n++) ar[n] = e[n] * inv;
        }
        __syncthreads();

        // ---- L3 (all 512): agg gather, max MLP ----
        for (int i = tid; i < SS * 25; i += 512) {
            int s = i / 25, q = i - s * 25;
            const float* ar = alph + s * NSN;
            const int*   nr = nid + s * NSN;
            float ax = 0.f, ay = 0.f, az = 0.f, aw = 0.f;
            float4 e[6];
            #pragma unroll
            for (int n = 0; n < 6; n++) e[n] = emb4[(ll)nr[n] * 25 + q];
            #pragma unroll
            for (int n = 0; n < 6; n++) {
                float al = ar[n];
                ax = fmaf(al, e[n].x, ax); ay = fmaf(al, e[n].y, ay);
                az = fmaf(al, e[n].z, az); aw = fmaf(al, e[n].w, aw);
            }
            #pragma unroll
            for (int n = 0; n < 6; n++) e[n] = emb4[(ll)nr[6 + n] * 25 + q];
            #pragma unroll
            for (int n = 0; n < 6; n++) {
                float al = ar[6 + n];
                ax = fmaf(al, e[n].x, ax); ay = fmaf(al, e[n].y, ay);
                az = fmaf(al, e[n].z, az); aw = fmaf(al, e[n].w, aw);
            }
            int d = 4 * q;
            AGG[(d + 0) * SS + s] = ax;
            AGG[(d + 1) * SS + s] = ay;
            AGG[(d + 2) * SS + s] = az;
            AGG[(d + 3) * SS + s] = aw;
        }
        __syncthreads();

        if (tid < 256) {
            // ======================= STAR half (barrier 1) =======================
            int st = tid;
            // P2: star = masked mean
            if (st < DD) {
                float s = 0.f;
                #pragma unroll 5
                for (int r = 0; r < SS; r++) s = fmaf(A[st * SS + r], msk[r], s);
                star[st] = s / denp[0];
            }
            barn(1);
            // P3 partial: skv halves -> C[0..199]
            if (st < 200) {
                int o = st % DD, hh = st / DD, base = hh * 50;
                const float* wc = Wk + o;
                float a0 = 0.f, a1 = 0.f, a2 = 0.f, a3 = 0.f, a4 = 0.f;
                #pragma unroll 5
                for (int j = 0; j < 10; j++) {
                    a0 = fmaf(star[base + j],      wc[(base + j) * DD],      a0);
                    a1 = fmaf(star[base + 10 + j], wc[(base + 10 + j) * DD], a1);
                    a2 = fmaf(star[base + 20 + j], wc[(base + 20 + j) * DD], a2);
                    a3 = fmaf(star[base + 30 + j], wc[(base + 30 + j) * DD], a3);
                    a4 = fmaf(star[base + 40 + j], wc[(base + 40 + j) * DD], a4);
                }
                C[st] = (((a0 + a1) + (a2 + a3)) + a4);
            }
            barn(1);
            if (st < DD) skv[st] = C[st] + C[DD + st];
            barn(1);
            // P4 partial: vv halves -> C[200..399]
            if (st < 200) {
                int o = st % DD, hh = st / DD, base = hh * 50;
                const float* wr = Wq + o * DD + base;
                float a0 = 0.f, a1 = 0.f, a2 = 0.f, a3 = 0.f, a4 = 0.f;
                #pragma unroll 5
                for (int j = 0; j < 10; j++) {
                    a0 = fmaf(wr[j],      skv[base + j],      a0);
                    a1 = fmaf(wr[10 + j], skv[base + 10 + j], a1);
                    a2 = fmaf(wr[20 + j], skv[base + 20 + j], a2);
                    a3 = fmaf(wr[30 + j], skv[base + 30 + j], a3);
                    a4 = fmaf(wr[40 + j], skv[base + 40 + j], a4);
                }
                C[200 + st] = (((a0 + a1) + (a2 + a3)) + a4);
            }
            barn(1);
            if (st < DD) vv[st] = C[200 + st] + C[300 + st];
            barn(1);
            // P5: gate (st<50) + GEMM1 hA = h @ Wa (st<250) -> C
            if (st < SS) {
                float a = 0.f;
                #pragma unroll 4
                for (int d = 0; d < DD; d++) a = fmaf(A[d * SS + st], vv[d], a);
                gate[st] = 1.f / (1.f + expf(-a * SCALEF));
            }
            if (st < 250) {
                int c2 = st % 50, g = st / 50, r0 = g * 10;
                ull acc[5][2];
                #pragma unroll
                for (int rp = 0; rp < 5; rp++) { acc[rp][0] = 0ull; acc[rp][1] = 0ull; }
                const ull* Au = (const ull*)A;
                #pragma unroll 5
                for (int k = 0; k < DD; k++) {
                    float2 w = *(const float2*)&Wa[k * DD + 2 * c2];
                    ull wlo = pack2(w.x, w.x), whi = pack2(w.y, w.y);
                    const ull* xr = Au + k * 25 + g * 5;
                    #pragma unroll
                    for (int rp = 0; rp < 5; rp++) {
                        ull xp = xr[rp];
                        ffma2(acc[rp][0], xp, wlo);
                        ffma2(acc[rp][1], xp, whi);
                    }
                }
                #pragma unroll
                for (int rp = 0; rp < 5; rp++) {
                    float v0, v1, u0, u1;
                    unpack2(acc[rp][0], v0, v1);
                    unpack2(acc[rp][1], u0, u1);
                    int r = r0 + 2 * rp;
                    C[r * DD + 2 * c2]           = v0;
                    C[(r + 1) * DD + 2 * c2]     = v1;
                    C[r * DD + 2 * c2 + 1]       = u0;
                    C[(r + 1) * DD + 2 * c2 + 1] = u1;
                }
            }
            barn(1);
            // P6: hn = adj @ hA (ADJP transposed -> LDS.128), hl = (1-g)*hn + g*star
            float hlv[10][2];
            int dp = st % 50, sg = st / 50, s0r = sg * 10;
            if (st < 250) {
                ull hn[10];
                #pragma unroll
                for (int j = 0; j < 10; j++) hn[j] = 0ull;
                const ull* Cu = (const ull*)C;
                const ull* Pu = (const ull*)ADJP;
                #pragma unroll 2
                for (int t = 0; t < SS; t++) {
                    ull xp = Cu[t * (DD / 2) + dp];
                    const ulonglong2* pr2 =
                        (const ulonglong2*)(Pu + t * SS + s0r);
                    #pragma unroll
                    for (int j2 = 0; j2 < 5; j2++) {
                        ulonglong2 pp = pr2[j2];
                        ffma2(hn[2 * j2],     xp, pp.x);
                        ffma2(hn[2 * j2 + 1], xp, pp.y);
                    }
                }
                float st0 = star[2 * dp], st1 = star[2 * dp + 1];
                #pragma unroll
                for (int j = 0; j < 10; j++) {
                    float h0, h1;
                    unpack2(hn[j], h0, h1);
                    float gg = gate[s0r + j];
                    hlv[j][0] = (1.f - gg) * h0 + gg * st0;
                    hlv[j][1] = (1.f - gg) * h1 + gg * st1;
                }
            }
            barn(1);   // all reads of C done
            if (st < 250) {
                #pragma unroll
                for (int j = 0; j < 10; j++) {
                    C[(s0r + j) * DD + 2 * dp]     = hlv[j][0];
                    C[(s0r + j) * DD + 2 * dp + 1] = hlv[j][1];
                }
            }
        } else {
            // ============ GLOBAL half: GEMM2, fused dual-pass k-loop ============
            int gt = tid - 256;
            ull acc[5][2];
            int c2 = gt % 50, g = gt / 50, r0 = g * 10;
            if (gt < 250) {
                #pragma unroll
                for (int rp = 0; rp < 5; rp++) { acc[rp][0] = 0ull; acc[rp][1] = 0ull; }
                const ull* Au = (const ull*)A;
                const ull* Bu = (const ull*)AGG;
                #pragma unroll 5
                for (int k = 0; k < DD; k++) {
                    float2 wA = *(const float2*)&Wg[k * DD + 2 * c2];
                    float2 wB = *(const float2*)&Wg[(DD + k) * DD + 2 * c2];
                    ull wAlo = pack2(wA.x, wA.x), wAhi = pack2(wA.y, wA.y);
                    ull wBlo = pack2(wB.x, wB.x), wBhi = pack2(wB.y, wB.y);
                    const ull* xrA = Au + k * 25 + g * 5;
                    const ull* xrB = Bu + k * 25 + g * 5;
                    #pragma unroll
                    for (int rp = 0; rp < 5; rp++) {
                        ull xpA = xrA[rp];
                        ull xpB = xrB[rp];
                        ffma2(acc[rp][0], xpA, wAlo);
                        ffma2(acc[rp][1], xpA, wAhi);
                        ffma2(acc[rp][0], xpB, wBlo);
                        ffma2(acc[rp][1], xpB, wBhi);
                    }
                }
            }
            barn(2);   // all AGG reads complete -> safe to overwrite with G
            if (gt < 250) {
                float* G = AGG;   // reuse
                #pragma unroll
                for (int rp = 0; rp < 5; rp++) {
                    float v0, v1, u0, u1;
                    unpack2(acc[rp][0], v0, v1);
                    unpack2(acc[rp][1], u0, u1);
                    int r = r0 + 2 * rp;
                    G[r * DD + 2 * c2]           = fmaxf(v0, 0.f);
                    G[(r + 1) * DD + 2 * c2]     = fmaxf(v1, 0.f);
                    G[r * DD + 2 * c2 + 1]       = fmaxf(u0, 0.f);
                    G[(r + 1) * DD + 2 * c2 + 1] = fmaxf(u1, 0.f);
                }
            }
        }
        __syncthreads();   // halves rendezvous: C = hl, AGG = G

        // ---- final combine: out = s0*l2n(hl) + s1*l2n(G), float4 path ----
        float* G = AGG;
        float s0 = sp[0], s1 = sp[1];
        int w = tid >> 5, lane = tid & 31;
        const float4* C4 = (const float4*)C;
        const float4* G4 = (const float4*)G;
        float4* out4 = (float4*)out;
        for (int r = w; r < SS; r += 16) {
            float4 x = make_float4(0.f, 0.f, 0.f, 0.f);
            float4 y = make_float4(0.f, 0.f, 0.f, 0.f);
            if (lane < 25) {
                x = C4[r * 25 + lane];
                y = G4[r * 25 + lane];
            }
            float ql = fmaf(x.x, x.x, fmaf(x.y, x.y, fmaf(x.z, x.z, x.w * x.w)));
            float qg = fmaf(y.x, y.x, fmaf(y.y, y.y, fmaf(y.z, y.z, y.w * y.w)));
            #pragma unroll
            for (int o = 16; o > 0; o >>= 1) {
                ql += __shfl_xor_sync(0xffffffffu, ql, o);
                qg += __shfl_xor_sync(0xffffffffu, qg, o);
            }
            float il = s0 / fmaxf(sqrtf(ql), 1e-12f);
            float ig = s1 / fmaxf(sqrtf(qg), 1e-12f);
            if (lane < 25) {
                float4 o4;
                o4.x = x.x * il + y.x * ig;
                o4.y = x.y * il + y.y * ig;
                o4.z = x.z * il + y.z * ig;
                o4.w = x.w * il + y.w * ig;
                out4[((ll)b * SS + r) * 25 + lane] = o4;
            }
        }
    } else {
        // ========================== LAST family ==========================
        int b = bid - BB;
        float* ith = sm;            // 300
        float* ah  = sm + 300;      // 3600
        float* q   = sm + 3900;     // 300
        float* att = sm + 4200;     // 36
        float* out_last = out + (ll)BB * SS * DD;

        for (int i = tid; i < LASTN * 25; i += 512) {
            int l = i / 25, qq = i - l * 25;
            ((float4*)ith)[i] = emb4[(ll)last_items[b * LASTN + l] * 25 + qq];
        }
        for (int i = tid; i < LASTN * NADJN * 25; i += 512) {
            int n = i / 25, qq = i - n * 25;
            ((float4*)ah)[i] = emb4[(ll)adj_items[b * LASTN * NADJN + n] * 25 + qq];
        }
        __syncthreads();

        if (tid < DD) {
            #pragma unroll
            for (int l = 0; l < LASTN; l++) {
                float a0 = 0.f, a1 = 0.f, a2 = 0.f, a3 = 0.f;
                #pragma unroll 5
                for (int k = 0; k < DD; k += 4) {
                    a0 = fmaf(ith[l * DD + k],     Wl[k * DD + tid],       a0);
                    a1 = fmaf(ith[l * DD + k + 1], Wl[(k + 1) * DD + tid], a1);
                    a2 = fmaf(ith[l * DD + k + 2], Wl[(k + 2) * DD + tid], a2);
                    a3 = fmaf(ith[l * DD + k + 3], Wl[(k + 3) * DD + tid], a3);
                }
                q[l * DD + tid] = (a0 + a1) + (a2 + a3);
            }
        }
        __syncthreads();

        int w = tid >> 5, lane = tid & 31;
        for (int p = w; p < LASTN * NADJN; p += 16) {
            int l = p / NADJN;
            float s = 0.f;
            for (int d = lane; d < DD; d += 32)
                s = fmaf(q[l * DD + d], ah[p * DD + d], s);
            #pragma unroll
            for (int o = 16; o > 0; o >>= 1)
                s += __shfl_xor_sync(0xffffffffu, s, o);
            if (lane == 0) att[p] = s * SCALEF;
        }
        __syncthreads();

        if (tid < LASTN) {
            float* ar = att + tid * NADJN;
            float m = ar[0];
            #pragma unroll
            for (int n = 1; n < NADJN; n++) m = fmaxf(m, ar[n]);
            float e[NADJN], s = 0.f;
            #pragma unroll
            for (int n = 0; n < NADJN; n++) { e[n] = expf(ar[n] - m); s += e[n]; }
            float inv = 1.f / s;
            #pragma unroll
            for (int n = 0; n < NADJN; n++) ar[n] = e[n] * inv;
        }
        __syncthreads();

        if (tid < DD) {
            float acc = 0.f;
            #pragma unroll
            for (int l = 0; l < LASTN; l++) {
                float a = ith[l * DD + tid];
                #pragma unroll
                for (int n = 0; n < NADJN; n++)
                    a = fmaf(att[l * NADJN + n], ah[(l * NADJN + n) * DD + tid], a);
                acc += a;
            }
            out_last[(ll)b * DD + tid] = acc * (1.f / 3.f);
        }
    }
}

extern "C" void kernel_launch(void* const* d_in, const int* in_sizes, int n_in,
                              void* d_out, int out_size)
{
    const int*   inputs     = (const int*)d_in[0];
    const float* adjm       = (const float*)d_in[1];
    /* d_in[2] = item (unused by the reference) */
    const int*   last_items = (const int*)d_in[3];
    const int*   adj_items  = (const int*)d_in[4];
    const float* emb        = (const float*)d_in[5];
    const float* sp         = (const float*)d_in[6];
    const float* Wa         = (const float*)d_in[7];
    const float* Wq         = (const float*)d_in[8];
    const float* Wk         = (const float*)d_in[9];
    const float* Wg         = (const float*)d_in[10];
    const float* Wl         = (const float*)d_in[11];
    const int*   adj_all    = (const int*)d_in[12];
    const float* num_w      = (const float*)d_in[13];
    float* out = (float*)d_out;

    cudaFuncSetAttribute(k_main, cudaFuncAttributeMaxDynamicSharedMemorySize,
                         SMEM_BYTES);
    k_main<<<2 * BB, 512, SMEM_BYTES>>>(inputs, adjm, last_items, adj_items,
                                        emb, sp, Wa, Wq, Wk, Wg, Wl,
                                        adj_all, num_w, out);
}